// round 13
// baseline (speedup 1.0000x reference)
#include <cuda_runtime.h>
#include <math.h>

#define IMG_W 1024
#define IMG_HW 1048576
#define PITCH 516    // words; 516 mod 32 == 4 -> LDS.128 bank-quad = k mod 8 (conflict-free)

// Cross-CTA accumulator: [image][kl*2+stat]. Zero at module load; finalize_kernel
// (sole reader) re-zeroes it after reading -> every launch/replay sees zeros.
__device__ float g_acc[32][128];

// Exact 8-point DCT-II (rows of the reference dct_matrix), even/odd butterfly.
__device__ __forceinline__ void dct8(const float x[8], float y[8]) {
    const float K1 = 0.4903926402016152f;
    const float K2 = 0.4619397662556434f;
    const float K3 = 0.4157348061512726f;
    const float K4 = 0.3535533905932738f;
    const float K5 = 0.2777851165098011f;
    const float K6 = 0.1913417161825449f;
    const float K7 = 0.0975451610080641f;
    float s0 = x[0] + x[7], s1 = x[1] + x[6], s2 = x[2] + x[5], s3 = x[3] + x[4];
    float d0 = x[0] - x[7], d1 = x[1] - x[6], d2 = x[2] - x[5], d3 = x[3] - x[4];
    float a = s0 + s3, b = s1 + s2, c = s0 - s3, e = s1 - s2;
    y[0] = K4 * (a + b);
    y[4] = K4 * (a - b);
    y[2] = K2 * c + K6 * e;
    y[6] = K6 * c - K2 * e;
    y[1] = K1 * d0 + K3 * d1 + K5 * d2 + K7 * d3;
    y[3] = K3 * d0 - K7 * d1 - K1 * d2 - K5 * d3;
    y[5] = K5 * d0 - K1 * d1 + K7 * d2 + K3 * d3;
    y[7] = K7 * d0 - K5 * d1 + K3 * d2 - K1 * d3;
}

// One CTA = one HALF-strip: (image, block-row, 512-column half) = 64 8x8 blocks.
// __launch_bounds__(256,5): 48-reg cap -> 5 CTAs/SM (40 warps) for deeper
// load pipelining on the HBM stream.
__global__ __launch_bounds__(256, 5) void dct_main(const float* __restrict__ img) {
    __shared__ float Yt[8 * PITCH];     // Yt[k*PITCH + col] : column-DCT output (512 cols)
    __shared__ float part[8][8][16];    // [warp][k][l*2 + stat]

    int t = threadIdx.x;
    int s = blockIdx.x;                 // half-strip id (0..8191)
    int b    = s >> 8;                  // image (0..31)
    int h    = s & 255;                 // half-strip within image
    int br   = h >> 1;                  // block row (0..127)
    int half = h & 1;                   // column half (0..1)
    const float* base = img + (size_t)b * 3 * IMG_HW + (size_t)br * 8 * IMG_W + half * 512;

    // ---- Phase 1: float2 streaming loads, luminance, 2 column-DCTs per thread ----
    {
        int col = t * 2;
        float2 X[8];
        #pragma unroll
        for (int i = 0; i < 8; i++) {
            const float* p = base + i * IMG_W + col;
            float2 r  = __ldcs((const float2*)(p));               // read-once
            float2 g  = __ldcs((const float2*)(p + IMG_HW));
            float2 bl = __ldcs((const float2*)(p + 2 * IMG_HW));
            // (0.299 r + 0.587 g + 0.114 b) * 255 (inputs uniform [0,1) -> scale 255)
            X[i].x = fmaf(76.245f, r.x, fmaf(149.685f, g.x, 29.07f * bl.x));
            X[i].y = fmaf(76.245f, r.y, fmaf(149.685f, g.y, 29.07f * bl.y));
        }
        float yc[2][8];
        {
            float x[8];
            #pragma unroll
            for (int i = 0; i < 8; i++) x[i] = X[i].x;
            dct8(x, yc[0]);
            #pragma unroll
            for (int i = 0; i < 8; i++) x[i] = X[i].y;
            dct8(x, yc[1]);
        }
        #pragma unroll
        for (int k = 0; k < 8; k++) {
            float2 v = make_float2(yc[0][k], yc[1][k]);
            *(float2*)&Yt[k * PITCH + col] = v;   // contiguous 8B per lane
        }
    }
    __syncthreads();

    // ---- Phase 2: row DCT + |c| / c^2 accumulation. Thread owns fixed k = t&7. ----
    int k = t & 7;
    float accs[8], accq[8];
    #pragma unroll
    for (int l = 0; l < 8; l++) { accs[l] = 0.f; accq[l] = 0.f; }

    #pragma unroll
    for (int q = 0; q < 2; q++) {
        int bc = (t >> 3) + q * 32;     // block-column 0..63
        float z[8];
        float4 za = *(const float4*)&Yt[k * PITCH + bc * 8];
        float4 zb = *(const float4*)&Yt[k * PITCH + bc * 8 + 4];
        z[0] = za.x; z[1] = za.y; z[2] = za.z; z[3] = za.w;
        z[4] = zb.x; z[5] = zb.y; z[6] = zb.z; z[7] = zb.w;
        float c[8];
        dct8(z, c);
        #pragma unroll
        for (int l = 0; l < 8; l++) {
            float v = c[l];
            accs[l] += fabsf(v);
            accq[l]  = fmaf(v, v, accq[l]);
        }
    }

    // Reduce over the 4 bc-groups within each warp (lanes {x, x^8, x^16, x^24} share k)
    #pragma unroll
    for (int l = 0; l < 8; l++) {
        accs[l] += __shfl_xor_sync(0xffffffffu, accs[l], 8);
        accs[l] += __shfl_xor_sync(0xffffffffu, accs[l], 16);
        accq[l] += __shfl_xor_sync(0xffffffffu, accq[l], 8);
        accq[l] += __shfl_xor_sync(0xffffffffu, accq[l], 16);
    }
    int warp = t >> 5, lane = t & 31;
    if (lane < 8) {
        #pragma unroll
        for (int l = 0; l < 8; l++) {
            part[warp][lane][2 * l]     = accs[l];
            part[warp][lane][2 * l + 1] = accq[l];
        }
    }
    __syncthreads();

    // 128 threads: sum 8 warps for one (k,l,stat) -> atomic into L2-resident g_acc
    if (t < 128) {
        int stat = t & 1, kl = t >> 1;
        int kk = kl >> 3, ll = kl & 7;
        float sm = 0.f;
        #pragma unroll
        for (int w = 0; w < 8; w++) sm += part[w][kk][2 * ll + stat];
        atomicAdd(&g_acc[b][t], sm);
    }
}

// One CTA per image, 512 threads (1 output each). Weights prefetched first;
// band stats parallelized: 64 threads (one per zigzag position) + 8-lane
// double shuffle reduction instead of an 8-thread x 16-add serial chain.
__global__ __launch_bounds__(512) void finalize_kernel(const int* __restrict__ zz,
                                                       const float* __restrict__ pw,
                                                       const float* __restrict__ pb,
                                                       float* __restrict__ out) {
    __shared__ float acc128[128];
    __shared__ float raw[16];
    int b = blockIdx.x, t = threadIdx.x;

    // Independent long-latency loads first (overlap everything below)
    const float4* w4 = (const float4*)(pw + t * 16);
    float4 w0 = w4[0], w1 = w4[1], w2 = w4[2], w3 = w4[3];
    float bias = pb[t];

    // zz for threads 0..63 (band = t>>3, position j = t&7)
    int kl = 0;
    if (t < 64) kl = zz[t];

    // Parallel staging of this image's accumulators (L2)
    if (t >= 64 && t < 192) acc128[t - 64] = __ldcg(&g_acc[b][t - 64]);
    __syncthreads();

    // Re-zero this image's accumulator slice for the next launch/replay
    if (t >= 64 && t < 192) g_acc[b][t - 64] = 0.f;

    if (t < 64) {
        double sS = (double)acc128[2 * kl];
        double sQ = (double)acc128[2 * kl + 1];
        // Reduce over the 8 zigzag positions of this band (lanes t..t^4 within 8-group)
        #pragma unroll
        for (int d = 4; d >= 1; d >>= 1) {
            sS += __shfl_xor_sync(0xffffffffu, sS, d);
            sQ += __shfl_xor_sync(0xffffffffu, sQ, d);
        }
        if ((t & 7) == 0) {
            int band = t >> 3;
            const double N = 131072.0;      // nh * nw * band_size
            double mean = sS / N;
            double var  = (sQ - sS * sS / N) / (N - 1.0);
            raw[band]     = (float)mean;
            raw[band + 8] = (float)(var > 0.0 ? sqrt(var) : 0.0);
        }
    }
    __syncthreads();

    // Projection: weights already in registers
    float acc = bias;
    acc = fmaf(raw[0],  w0.x, acc); acc = fmaf(raw[1],  w0.y, acc);
    acc = fmaf(raw[2],  w0.z, acc); acc = fmaf(raw[3],  w0.w, acc);
    acc = fmaf(raw[4],  w1.x, acc); acc = fmaf(raw[5],  w1.y, acc);
    acc = fmaf(raw[6],  w1.z, acc); acc = fmaf(raw[7],  w1.w, acc);
    acc = fmaf(raw[8],  w2.x, acc); acc = fmaf(raw[9],  w2.y, acc);
    acc = fmaf(raw[10], w2.z, acc); acc = fmaf(raw[11], w2.w, acc);
    acc = fmaf(raw[12], w3.x, acc); acc = fmaf(raw[13], w3.y, acc);
    acc = fmaf(raw[14], w3.z, acc); acc = fmaf(raw[15], w3.w, acc);
    out[b * 512 + t] = acc;
}

extern "C" void kernel_launch(void* const* d_in, const int* in_sizes, int n_in,
                              void* d_out, int out_size) {
    const float* img = (const float*)d_in[0];
    // d_in[1] = dct_matrix (hardcoded exactly via butterfly)
    const int*   zz  = (const int*)d_in[2];
    const float* pw  = (const float*)d_in[3];
    const float* pb  = (const float*)d_in[4];

    dct_main<<<8192, 256>>>(img);
    finalize_kernel<<<32, 512>>>(zz, pw, pb, (float*)d_out);
}

// round 14
// speedup vs baseline: 1.0656x; 1.0656x over previous
#include <cuda_runtime.h>
#include <math.h>

#define IMG_W 1024
#define IMG_HW 1048576
#define PITCH 516    // words; 516 mod 32 == 4 -> LDS.128 bank-quad = k mod 8 (conflict-free)

// Cross-CTA accumulator: [image][kl*2+stat]. Zero at module load; finalize_kernel
// (sole reader) re-zeroes it after reading -> every launch/replay sees zeros.
__device__ float g_acc[32][128];

// Exact 8-point DCT-II (rows of the reference dct_matrix), even/odd butterfly.
__device__ __forceinline__ void dct8(const float x[8], float y[8]) {
    const float K1 = 0.4903926402016152f;
    const float K2 = 0.4619397662556434f;
    const float K3 = 0.4157348061512726f;
    const float K4 = 0.3535533905932738f;
    const float K5 = 0.2777851165098011f;
    const float K6 = 0.1913417161825449f;
    const float K7 = 0.0975451610080641f;
    float s0 = x[0] + x[7], s1 = x[1] + x[6], s2 = x[2] + x[5], s3 = x[3] + x[4];
    float d0 = x[0] - x[7], d1 = x[1] - x[6], d2 = x[2] - x[5], d3 = x[3] - x[4];
    float a = s0 + s3, b = s1 + s2, c = s0 - s3, e = s1 - s2;
    y[0] = K4 * (a + b);
    y[4] = K4 * (a - b);
    y[2] = K2 * c + K6 * e;
    y[6] = K6 * c - K2 * e;
    y[1] = K1 * d0 + K3 * d1 + K5 * d2 + K7 * d3;
    y[3] = K3 * d0 - K7 * d1 - K1 * d2 - K5 * d3;
    y[5] = K5 * d0 - K1 * d1 + K7 * d2 + K3 * d3;
    y[7] = K7 * d0 - K5 * d1 + K3 * d2 - K1 * d3;
}

// One CTA = one HALF-strip: (image, block-row, 512-column half) = 64 8x8 blocks.
// __launch_bounds__(256,4): proven sweet spot — ~50 regs, 4 CTAs/SM (32 warps),
// no spills. (256,5) forces spills and regresses; (256,3) underutilizes HBM.
__global__ __launch_bounds__(256, 4) void dct_main(const float* __restrict__ img) {
    __shared__ float Yt[8 * PITCH];     // Yt[k*PITCH + col] : column-DCT output (512 cols)
    __shared__ float part[8][8][16];    // [warp][k][l*2 + stat]

    int t = threadIdx.x;
    int s = blockIdx.x;                 // half-strip id (0..8191)
    int b    = s >> 8;                  // image (0..31)
    int h    = s & 255;                 // half-strip within image
    int br   = h >> 1;                  // block row (0..127)
    int half = h & 1;                   // column half (0..1)
    const float* base = img + (size_t)b * 3 * IMG_HW + (size_t)br * 8 * IMG_W + half * 512;

    // ---- Phase 1: float2 streaming loads, luminance, 2 column-DCTs per thread ----
    {
        int col = t * 2;
        float2 X[8];
        #pragma unroll
        for (int i = 0; i < 8; i++) {
            const float* p = base + i * IMG_W + col;
            float2 r  = __ldcs((const float2*)(p));               // read-once
            float2 g  = __ldcs((const float2*)(p + IMG_HW));
            float2 bl = __ldcs((const float2*)(p + 2 * IMG_HW));
            // (0.299 r + 0.587 g + 0.114 b) * 255 (inputs uniform [0,1) -> scale 255)
            X[i].x = fmaf(76.245f, r.x, fmaf(149.685f, g.x, 29.07f * bl.x));
            X[i].y = fmaf(76.245f, r.y, fmaf(149.685f, g.y, 29.07f * bl.y));
        }
        float yc[2][8];
        {
            float x[8];
            #pragma unroll
            for (int i = 0; i < 8; i++) x[i] = X[i].x;
            dct8(x, yc[0]);
            #pragma unroll
            for (int i = 0; i < 8; i++) x[i] = X[i].y;
            dct8(x, yc[1]);
        }
        #pragma unroll
        for (int k = 0; k < 8; k++) {
            float2 v = make_float2(yc[0][k], yc[1][k]);
            *(float2*)&Yt[k * PITCH + col] = v;   // contiguous 8B per lane
        }
    }
    __syncthreads();

    // ---- Phase 2: row DCT + |c| / c^2 accumulation. Thread owns fixed k = t&7. ----
    int k = t & 7;
    float accs[8], accq[8];
    #pragma unroll
    for (int l = 0; l < 8; l++) { accs[l] = 0.f; accq[l] = 0.f; }

    #pragma unroll
    for (int q = 0; q < 2; q++) {
        int bc = (t >> 3) + q * 32;     // block-column 0..63
        float z[8];
        float4 za = *(const float4*)&Yt[k * PITCH + bc * 8];
        float4 zb = *(const float4*)&Yt[k * PITCH + bc * 8 + 4];
        z[0] = za.x; z[1] = za.y; z[2] = za.z; z[3] = za.w;
        z[4] = zb.x; z[5] = zb.y; z[6] = zb.z; z[7] = zb.w;
        float c[8];
        dct8(z, c);
        #pragma unroll
        for (int l = 0; l < 8; l++) {
            float v = c[l];
            accs[l] += fabsf(v);
            accq[l]  = fmaf(v, v, accq[l]);
        }
    }

    // Reduce over the 4 bc-groups within each warp (lanes {x, x^8, x^16, x^24} share k)
    #pragma unroll
    for (int l = 0; l < 8; l++) {
        accs[l] += __shfl_xor_sync(0xffffffffu, accs[l], 8);
        accs[l] += __shfl_xor_sync(0xffffffffu, accs[l], 16);
        accq[l] += __shfl_xor_sync(0xffffffffu, accq[l], 8);
        accq[l] += __shfl_xor_sync(0xffffffffu, accq[l], 16);
    }
    int warp = t >> 5, lane = t & 31;
    if (lane < 8) {
        #pragma unroll
        for (int l = 0; l < 8; l++) {
            part[warp][lane][2 * l]     = accs[l];
            part[warp][lane][2 * l + 1] = accq[l];
        }
    }
    __syncthreads();

    // 128 threads: sum 8 warps for one (k,l,stat) -> atomic into L2-resident g_acc
    if (t < 128) {
        int stat = t & 1, kl = t >> 1;
        int kk = kl >> 3, ll = kl & 7;
        float sm = 0.f;
        #pragma unroll
        for (int w = 0; w < 8; w++) sm += part[w][kk][2 * ll + stat];
        atomicAdd(&g_acc[b][t], sm);
    }
}

// One CTA per image, 512 threads (1 output each). Weights prefetched first;
// band stats parallelized: 64 threads (one per zigzag position) + 8-lane
// double shuffle reduction instead of an 8-thread x 16-add serial chain.
__global__ __launch_bounds__(512) void finalize_kernel(const int* __restrict__ zz,
                                                       const float* __restrict__ pw,
                                                       const float* __restrict__ pb,
                                                       float* __restrict__ out) {
    __shared__ float acc128[128];
    __shared__ float raw[16];
    int b = blockIdx.x, t = threadIdx.x;

    // Independent long-latency loads first (overlap everything below)
    const float4* w4 = (const float4*)(pw + t * 16);
    float4 w0 = w4[0], w1 = w4[1], w2 = w4[2], w3 = w4[3];
    float bias = pb[t];

    // zz for threads 0..63 (band = t>>3, position j = t&7)
    int kl = 0;
    if (t < 64) kl = zz[t];

    // Parallel staging of this image's accumulators (L2)
    if (t >= 64 && t < 192) acc128[t - 64] = __ldcg(&g_acc[b][t - 64]);
    __syncthreads();

    // Re-zero this image's accumulator slice for the next launch/replay
    if (t >= 64 && t < 192) g_acc[b][t - 64] = 0.f;

    if (t < 64) {
        double sS = (double)acc128[2 * kl];
        double sQ = (double)acc128[2 * kl + 1];
        // Reduce over the 8 zigzag positions of this band (xor lanes within 8-group)
        #pragma unroll
        for (int d = 4; d >= 1; d >>= 1) {
            sS += __shfl_xor_sync(0xffffffffu, sS, d);
            sQ += __shfl_xor_sync(0xffffffffu, sQ, d);
        }
        if ((t & 7) == 0) {
            int band = t >> 3;
            const double N = 131072.0;      // nh * nw * band_size
            double mean = sS / N;
            double var  = (sQ - sS * sS / N) / (N - 1.0);
            raw[band]     = (float)mean;
            raw[band + 8] = (float)(var > 0.0 ? sqrt(var) : 0.0);
        }
    }
    __syncthreads();

    // Projection: weights already in registers
    float acc = bias;
    acc = fmaf(raw[0],  w0.x, acc); acc = fmaf(raw[1],  w0.y, acc);
    acc = fmaf(raw[2],  w0.z, acc); acc = fmaf(raw[3],  w0.w, acc);
    acc = fmaf(raw[4],  w1.x, acc); acc = fmaf(raw[5],  w1.y, acc);
    acc = fmaf(raw[6],  w1.z, acc); acc = fmaf(raw[7],  w1.w, acc);
    acc = fmaf(raw[8],  w2.x, acc); acc = fmaf(raw[9],  w2.y, acc);
    acc = fmaf(raw[10], w2.z, acc); acc = fmaf(raw[11], w2.w, acc);
    acc = fmaf(raw[12], w3.x, acc); acc = fmaf(raw[13], w3.y, acc);
    acc = fmaf(raw[14], w3.z, acc); acc = fmaf(raw[15], w3.w, acc);
    out[b * 512 + t] = acc;
}

extern "C" void kernel_launch(void* const* d_in, const int* in_sizes, int n_in,
                              void* d_out, int out_size) {
    const float* img = (const float*)d_in[0];
    // d_in[1] = dct_matrix (hardcoded exactly via butterfly)
    const int*   zz  = (const int*)d_in[2];
    const float* pw  = (const float*)d_in[3];
    const float* pb  = (const float*)d_in[4];

    dct_main<<<8192, 256>>>(img);
    finalize_kernel<<<32, 512>>>(zz, pw, pb, (float*)d_out);
}